// round 14
// baseline (speedup 1.0000x reference)
#include <cuda_runtime.h>
#include <cstdint>

// Problem constants
#define NN 100000
#define EE 3200000
#define FIN 512
#define HH 16
#define CC 40
#define CAP 128            // max in-degree slots per node (Poisson(32); P(>128)~1e-40)

// ---------------- scratch (device globals, referenced DIRECTLY) -------------
__device__ float g_h0[NN * HH];
__device__ float g_h1[NN * HH];
__device__ float g_agg[NN * HH];
__device__ float g_dinv[NN];
__device__ int   g_cnt[NN];
__device__ int2  g_bucket[(size_t)NN * CAP];   // (src, ew-bits) per slot

// ---------------- packed f32x2 helpers --------------------------------------
__device__ __forceinline__ unsigned long long pack2(float v) {
    unsigned long long r;
    asm("mov.b64 %0, {%1,%1};" : "=l"(r) : "f"(v));
    return r;
}
__device__ __forceinline__ void fma2(unsigned long long& acc,
                                     unsigned long long a, unsigned long long b) {
    asm("fma.rn.f32x2 %0, %1, %2, %0;" : "+l"(acc) : "l"(a), "l"(b));
}
__device__ __forceinline__ void add2(unsigned long long& a, unsigned long long b) {
    asm("add.rn.f32x2 %0, %0, %1;" : "+l"(a) : "l"(b));
}
__device__ __forceinline__ float lo2(unsigned long long v) {
    return __uint_as_float((unsigned)(v & 0xffffffffu));
}
__device__ __forceinline__ float hi2(unsigned long long v) {
    return __uint_as_float((unsigned)(v >> 32));
}

// ---------------- init ------------------------------------------------------
__global__ void k_init() {
    int i = blockIdx.x * blockDim.x + threadIdx.x;
    if (i < NN) g_cnt[i] = 0;
}

// ---------------- bucket placement: ONE pass, cursor == count ---------------
__global__ void k_place(const int* __restrict__ ei, const float* __restrict__ ew) {
    int e = blockIdx.x * blockDim.x + threadIdx.x;
    if (e >= EE) return;
    int r = ei[e];        // source
    int c = ei[EE + e];   // target
    int pos = atomicAdd(&g_cnt[c], 1);
    g_bucket[(size_t)c * CAP + pos] = make_int2(r, __float_as_int(ew[e]));
}

// ---------------- weighted degree + dinv: coalesced segment sum, no atomics -
__global__ void k_segdinv() {
    int node = (blockIdx.x * blockDim.x + threadIdx.x) >> 5;
    if (node >= NN) return;
    int lane = threadIdx.x & 31;
    int n = g_cnt[node];
    const int2* bk = g_bucket + (size_t)node * CAP;
    float s = 0.0f;
    for (int i = lane; i < n; i += 32) s += __int_as_float(bk[i].y);
#pragma unroll
    for (int o = 16; o > 0; o >>= 1) s += __shfl_xor_sync(0xffffffffu, s, o);
    if (lane == 0) g_dinv[node] = rsqrtf(1.0f + s);   // +1 = self-loop weight
}

// ---------------- fc1: g_h0 = relu(x @ W_first + b_first) -------------------
// 4 rows per warp; coalesced x; W smem row stride 18 floats (conflict-free
// for LDS.64 at k = lane + 32t); packed f32x2 FMAs, W amortized over 4 rows.
#define FC1_TB 256
#define WST 18
__global__ void __launch_bounds__(FC1_TB)
k_fc1(const float* __restrict__ x, const float* __restrict__ W,
      const float* __restrict__ b) {
    __shared__ float Wsh[FIN * WST];   // 36.9 KB
    for (int i = threadIdx.x; i < FIN * HH; i += FC1_TB) {
        int k = i >> 4, j = i & 15;
        Wsh[k * WST + j] = W[i];
    }
    __syncthreads();

    int warp = threadIdx.x >> 5, lane = threadIdx.x & 31;
    int row0 = blockIdx.x * 32 + warp * 4;            // 8 warps x 4 rows
    if (row0 >= NN) return;

    unsigned long long acc[4][8];
#pragma unroll
    for (int rr = 0; rr < 4; rr++)
#pragma unroll
        for (int p = 0; p < 8; p++) acc[rr][p] = 0ull;

    // two halves of k to bound live x registers
#pragma unroll
    for (int half = 0; half < 2; half++) {
        float xv[4][8];
#pragma unroll
        for (int rr = 0; rr < 4; rr++) {
            const float* xr = x + (size_t)(row0 + rr) * FIN + half * 256;
#pragma unroll
            for (int t = 0; t < 8; t++) xv[rr][t] = xr[lane + 32 * t];
        }
#pragma unroll
        for (int t = 0; t < 8; t++) {
            int k = lane + 32 * t + half * 256;
            const unsigned long long* wr = (const unsigned long long*)(Wsh + k * WST);
            unsigned long long w[8];
#pragma unroll
            for (int p = 0; p < 8; p++) w[p] = wr[p];
#pragma unroll
            for (int rr = 0; rr < 4; rr++) {
                unsigned long long px = pack2(xv[rr][t]);
#pragma unroll
                for (int p = 0; p < 8; p++) fma2(acc[rr][p], px, w[p]);
            }
        }
    }

    float bb[16];
#pragma unroll
    for (int j = 0; j < 16; j++) bb[j] = __ldg(&b[j]);

#pragma unroll
    for (int rr = 0; rr < 4; rr++) {
#pragma unroll
        for (int p = 0; p < 8; p++) {
            unsigned long long v = acc[rr][p];
#pragma unroll
            for (int s = 16; s > 0; s >>= 1) {
                unsigned long long o = __shfl_xor_sync(0xffffffffu, v, s);
                add2(v, o);
            }
            acc[rr][p] = v;
        }
        if (lane == 0) {
            float4* dst = (float4*)(g_h0 + (size_t)(row0 + rr) * HH);
#pragma unroll
            for (int q = 0; q < 4; q++) {
                float a0 = (q * 2 + 0 < 8) ? lo2(acc[rr][2 * q]) : 0.0f;
                (void)a0;
                dst[q] = make_float4(
                    fmaxf(lo2(acc[rr][2 * q]) + bb[4 * q + 0], 0.0f),
                    fmaxf(hi2(acc[rr][2 * q]) + bb[4 * q + 1], 0.0f),
                    fmaxf(lo2(acc[rr][2 * q + 1]) + bb[4 * q + 2], 0.0f),
                    fmaxf(hi2(acc[rr][2 * q + 1]) + bb[4 * q + 3], 0.0f));
            }
        }
    }
}

// ---------------- fused gather + 16x16 linear, nrm on the fly ---------------
// out_node = [relu]( (A_norm . h)_node @ W [+ bias] )
// acc = sum_e (dinv[src]*ew) h[src]; result = dinv_n*acc + dinv_n^2*h[node]
__device__ __forceinline__ float* buf(int id) {
    return (id == 0) ? g_h0 : (id == 1) ? g_h1 : g_agg;
}

template <int IN, int OUT, bool BIAS_RELU>
__global__ void __launch_bounds__(256)
k_g(const float* __restrict__ W, const float* __restrict__ bias) {
    __shared__ float Wsh[HH * HH];
    __shared__ float bsh[HH];
    if (threadIdx.x < HH * HH) Wsh[threadIdx.x] = W[threadIdx.x];
    if (BIAS_RELU && threadIdx.x < HH) bsh[threadIdx.x] = bias[threadIdx.x];
    __syncthreads();

    int node = (blockIdx.x * blockDim.x + threadIdx.x) >> 5;
    if (node >= NN) return;
    int lane = threadIdx.x & 31;
    int eg = lane >> 2;   // 0..7
    int f  = lane & 3;    // float4 column 0..3
    int n = g_cnt[node];
    const int2* bk = g_bucket + (size_t)node * CAP;
    const float4* h = (const float4*)buf(IN);

    float ax = 0.0f, ay = 0.0f, az = 0.0f, aw = 0.0f;
    for (int i = eg; i < n; i += 8) {
        int2 e = bk[i];
        float w = g_dinv[e.x] * __int_as_float(e.y);
        float4 t = h[(size_t)e.x * 4 + f];
        ax += t.x * w; ay += t.y * w; az += t.z * w; aw += t.w * w;
    }
    // reduce across the 8 edge groups
#pragma unroll
    for (int s = 4; s < 32; s <<= 1) {
        ax += __shfl_xor_sync(0xffffffffu, ax, s);
        ay += __shfl_xor_sync(0xffffffffu, ay, s);
        az += __shfl_xor_sync(0xffffffffu, az, s);
        aw += __shfl_xor_sync(0xffffffffu, aw, s);
    }
    // scale by dinv_node, add self loop dinv_node^2 * h[node]
    {
        float d = g_dinv[node];
        float4 t = h[(size_t)node * 4 + f];
        ax = d * ax + d * d * t.x;
        ay = d * ay + d * d * t.y;
        az = d * az + d * d * t.z;
        aw = d * aw + d * d * t.w;
    }
    // broadcast full 16-vector: v[4q+m] from lane q
    float v[16];
#pragma unroll
    for (int q = 0; q < 4; q++) {
        v[4 * q + 0] = __shfl_sync(0xffffffffu, ax, q);
        v[4 * q + 1] = __shfl_sync(0xffffffffu, ay, q);
        v[4 * q + 2] = __shfl_sync(0xffffffffu, az, q);
        v[4 * q + 3] = __shfl_sync(0xffffffffu, aw, q);
    }
    // epilogue matmul: lane f computes outputs 4f..4f+3
    float o0 = 0.0f, o1 = 0.0f, o2 = 0.0f, o3 = 0.0f;
#pragma unroll
    for (int k = 0; k < 16; k++) {
        const float4 w = ((const float4*)Wsh)[k * 4 + f];
        o0 += v[k] * w.x; o1 += v[k] * w.y; o2 += v[k] * w.z; o3 += v[k] * w.w;
    }
    if (BIAS_RELU) {
        o0 = fmaxf(o0 + bsh[4 * f + 0], 0.0f);
        o1 = fmaxf(o1 + bsh[4 * f + 1], 0.0f);
        o2 = fmaxf(o2 + bsh[4 * f + 2], 0.0f);
        o3 = fmaxf(o3 + bsh[4 * f + 3], 0.0f);
    }
    if (eg == 0) {
        ((float4*)buf(OUT))[(size_t)node * 4 + f] = make_float4(o0, o1, o2, o3);
    }
}

// ---------------- output layer: relu(g_agg+b2) @ W_out + b_out, log_softmax -
__global__ void k_out(const float* __restrict__ b2, const float* __restrict__ Wout,
                      const float* __restrict__ bout, float* __restrict__ out) {
    __shared__ float Wsh[HH * CC];
    __shared__ float bosh[CC];
    __shared__ float b2sh[HH];
    for (int i = threadIdx.x; i < HH * CC; i += blockDim.x) Wsh[i] = Wout[i];
    if (threadIdx.x < CC) bosh[threadIdx.x] = bout[threadIdx.x];
    if (threadIdx.x < HH) b2sh[threadIdx.x] = b2[threadIdx.x];
    __syncthreads();

    int r = blockIdx.x * blockDim.x + threadIdx.x;
    if (r >= NN) return;

    float v[16];
    const float4* ir = (const float4*)(g_agg + (size_t)r * HH);
#pragma unroll
    for (int q = 0; q < 4; q++) {
        float4 t = ir[q];
        v[4 * q] = t.x; v[4 * q + 1] = t.y; v[4 * q + 2] = t.z; v[4 * q + 3] = t.w;
    }
#pragma unroll
    for (int j = 0; j < 16; j++) v[j] = fmaxf(v[j] + b2sh[j], 0.0f);

    float lg[CC];
#pragma unroll
    for (int j = 0; j < CC; j++) lg[j] = bosh[j];
#pragma unroll
    for (int k = 0; k < 16; k++) {
        float vk = v[k];
        const float* wr = &Wsh[k * CC];
#pragma unroll
        for (int j = 0; j < CC; j++) lg[j] += vk * wr[j];
    }
    float m = lg[0];
#pragma unroll
    for (int j = 1; j < CC; j++) m = fmaxf(m, lg[j]);
    float s = 0.0f;
#pragma unroll
    for (int j = 0; j < CC; j++) s += __expf(lg[j] - m);
    float ls = __logf(s) + m;
    float* orow = out + (size_t)r * CC;
#pragma unroll
    for (int j = 0; j < CC; j++) orow[j] = lg[j] - ls;
}

// ---------------- launch: ONLY kernel launches ------------------------------
extern "C" void kernel_launch(void* const* d_in, const int* in_sizes, int n_in,
                              void* d_out, int out_size) {
    const float* x       = (const float*)d_in[0];
    const int*   ei      = (const int*)d_in[1];     // int32 (2, E) row-major
    const float* ew      = (const float*)d_in[2];
    const float* W_first = (const float*)d_in[3];
    const float* b_first = (const float*)d_in[4];
    const float* W_c1    = (const float*)d_in[5];
    const float* b_c1    = (const float*)d_in[6];
    const float* W_c2    = (const float*)d_in[7];
    const float* b_c2    = (const float*)d_in[8];
    const float* W_out   = (const float*)d_in[9];
    const float* b_out   = (const float*)d_in[10];
    float* out = (float*)d_out;

    const int TB = 256;
    int gN = (NN + TB - 1) / TB;
    int gE = (EE + TB - 1) / TB;
    int gW = (NN * 32 + TB - 1) / TB;  // warp per node

    k_init<<<gN, TB>>>();
    k_place<<<gE, TB>>>(ei, ew);
    k_segdinv<<<gW, TB>>>();

    // fc1 -> g_h0 (32 rows per block)
    k_fc1<<<(NN + 31) / 32, FC1_TB>>>(x, W_first, b_first);

    // conv1 fused: g_h1 = relu((A . g_h0) @ W_c1 + b_c1)
    k_g<0, 1, true><<<gW, TB>>>(W_c1, b_c1);
    // conv2 fused: g_agg = (A . g_h1) @ W_c2   (bias+relu applied in k_out)
    k_g<1, 2, false><<<gW, TB>>>(W_c2, nullptr);

    // output layer
    k_out<<<gN, TB>>>(b_c2, W_out, b_out, out);
}